// round 4
// baseline (speedup 1.0000x reference)
#include <cuda_runtime.h>
#include <cstdint>

#define SEQ 2048
#define BATCH 128
#define IND 64
#define HID 256
#define OUTD 64
#define S_CTAS 8        // cluster size = hidden-slice CTAs per batch group
#define BG 8            // batch elements per group
#define UPC 32          // hidden units per CTA (HID / S_CTAS)
#define KTOT 320        // HID + IND (concatenated [h | x] dot length)
#define WSTR 324        // padded row stride in floats (mod 32 == 4 -> conflict-free)
#define OSTR 260        // padded W_out row stride
#define NTHREADS 256

// shared memory layout (in floats)
#define SM_WS   0                         // 128 rows x WSTR  (W_hh|W_ih slice)
#define SM_HX   (128 * WSTR)              // 2 buffers x BG x WSTR ([h|x] per batch)
#define SM_WOUT (SM_HX + 2 * BG * WSTR)   // 8 rows x OSTR (W_out slice)
#define SM_FLOATS (SM_WOUT + 8 * OSTR)
#define SM_BYTES (SM_FLOATS * 4)          // 194944 bytes

__device__ __forceinline__ uint32_t s2u(const void* p) {
    uint32_t a;
    asm("{ .reg .u64 t; cvta.to.shared.u64 t, %1; cvt.u32.u64 %0, t; }"
        : "=r"(a) : "l"(p));
    return a;
}
__device__ __forceinline__ unsigned long long ffma2(unsigned long long a,
                                                    unsigned long long b,
                                                    unsigned long long c) {
    unsigned long long d;
    asm("fma.rn.f32x2 %0, %1, %2, %3;" : "=l"(d) : "l"(a), "l"(b), "l"(c));
    return d;
}
__device__ __forceinline__ unsigned long long pk2(float x, float y) {
    unsigned long long r;
    asm("mov.b64 %0, {%1,%2};" : "=l"(r) : "f"(x), "f"(y));
    return r;
}
__device__ __forceinline__ float hsum2(unsigned long long v) {
    float x, y;
    asm("mov.b64 {%0,%1}, %2;" : "=f"(x), "=f"(y) : "l"(v));
    return x + y;
}

extern "C" __global__ void __cluster_dims__(S_CTAS, 1, 1) __launch_bounds__(NTHREADS, 1)
lstm_persistent_kernel(const float* __restrict__ x,
                       const float* __restrict__ h0,
                       const float* __restrict__ c0,
                       const float* __restrict__ W_ih,
                       const float* __restrict__ W_hh,
                       const float* __restrict__ bias,
                       const float* __restrict__ W_out,
                       const float* __restrict__ b_out,
                       float* __restrict__ out) {
    extern __shared__ float sm[];
    float* ws   = sm + SM_WS;
    float* hx0  = sm + SM_HX;
    float* hx1  = hx0 + BG * WSTR;
    float* wout = sm + SM_WOUT;

    const int tid = threadIdx.x;
    const int g   = blockIdx.x / S_CTAS;   // batch group
    uint32_t s;
    asm("mov.u32 %0, %%cluster_ctarank;" : "=r"(s));
    const int b0 = g * BG;
    const int u  = tid >> 3;               // hidden unit within slice (0..31)
    const int bb = tid & 7;                // batch within group (0..7)

    // ---------------- one-time init: weights / state into SMEM ----------------
    // combined gate rows: row r = gate*32 + uu -> global gate row gate*HID + s*32 + uu
    for (int i = tid; i < 128 * KTOT; i += NTHREADS) {
        int r = i / KTOT, k = i - r * KTOT;
        int gate = r >> 5, uu = r & 31;
        int grow = gate * HID + (int)s * UPC + uu;
        float v = (k < HID) ? W_hh[grow * HID + k] : W_ih[grow * IND + (k - HID)];
        ws[r * WSTR + k] = v;
    }
    for (int i = tid; i < 8 * HID; i += NTHREADS) {
        int oo = i >> 8, k = i & 255;
        wout[oo * OSTR + k] = W_out[((int)s * 8 + oo) * HID + k];
    }
    // h0 into buffer 0 (full h for this batch group)
    for (int i = tid; i < BG * HID; i += NTHREADS) {
        int bbx = i >> 8, k = i & 255;
        hx0[bbx * WSTR + k] = h0[(b0 + bbx) * HID + k];
    }
    // x_0 into buffer 0 x-section
    for (int i = tid; i < BG * IND; i += NTHREADS) {
        int bbx = i >> 6, k = i & 63;
        hx0[bbx * WSTR + HID + k] = x[(size_t)(b0 + bbx) * IND + k];
    }
    // per-thread constants
    float c_st = c0[(b0 + bb) * HID + (int)s * UPC + u];
    const float bi = bias[0 * HID + (int)s * UPC + u];
    const float bf = bias[1 * HID + (int)s * UPC + u];
    const float bg = bias[2 * HID + (int)s * UPC + u];
    const float bo = bias[3 * HID + (int)s * UPC + u];
    const int oo = tid & 7;        // readout: output column within slice
    const int ob = tid >> 3;       // readout: batch index (valid for tid<64)
    const float bout = (tid < 64) ? b_out[(int)s * 8 + oo] : 0.f;

    __syncthreads();
    asm volatile("barrier.cluster.arrive.aligned;" ::: "memory");
    asm volatile("barrier.cluster.wait.aligned;" ::: "memory");

    const uint32_t smem_b = s2u(sm);
    const int jmine = (int)s * UPC + u;    // my global hidden index

    const ulonglong2* wp0 = (const ulonglong2*)(ws + (0 * UPC + u) * WSTR);
    const ulonglong2* wp1 = (const ulonglong2*)(ws + (1 * UPC + u) * WSTR);
    const ulonglong2* wp2 = (const ulonglong2*)(ws + (2 * UPC + u) * WSTR);
    const ulonglong2* wp3 = (const ulonglong2*)(ws + (3 * UPC + u) * WSTR);

    for (int t = 0; t < SEQ; ++t) {
        float* cur = (t & 1) ? hx1 : hx0;
        float* nxt = (t & 1) ? hx0 : hx1;

        // ---- gate dots over K = 320 ([h_{t-1} | x_t]), packed f32x2 FMA ----
        const ulonglong2* hp = (const ulonglong2*)(cur + bb * WSTR);
        unsigned long long a0 = pk2(bi, 0.f);
        unsigned long long a1 = pk2(bf, 0.f);
        unsigned long long a2 = pk2(bg, 0.f);
        unsigned long long a3 = pk2(bo, 0.f);
        #pragma unroll 8
        for (int k = 0; k < KTOT / 4; ++k) {
            ulonglong2 h = hp[k];
            ulonglong2 w;
            w = wp0[k]; a0 = ffma2(w.x, h.x, a0); a0 = ffma2(w.y, h.y, a0);
            w = wp1[k]; a1 = ffma2(w.x, h.x, a1); a1 = ffma2(w.y, h.y, a1);
            w = wp2[k]; a2 = ffma2(w.x, h.x, a2); a2 = ffma2(w.y, h.y, a2);
            w = wp3[k]; a3 = ffma2(w.x, h.x, a3); a3 = ffma2(w.y, h.y, a3);
        }
        float li = hsum2(a0), lf = hsum2(a1), lg = hsum2(a2), lo = hsum2(a3);

        // ---- LSTM cell epilogue (eqx gate order i,f,g,o) ----
        float ig = 1.f / (1.f + __expf(-li));
        float fg = 1.f / (1.f + __expf(-lf));
        float gg = tanhf(lg);
        float og = 1.f / (1.f + __expf(-lo));
        c_st = fg * c_st + ig * gg;
        float hn = og * tanhf(c_st);

        // ---- scatter h_t to every cluster CTA's next buffer (DSMEM) ----
        uint32_t loc = smem_b + (uint32_t)((nxt - sm) + bb * WSTR + jmine) * 4u;
        #pragma unroll
        for (int r = 0; r < S_CTAS; ++r) {
            uint32_t ra;
            asm("mapa.shared::cluster.u32 %0, %1, %2;" : "=r"(ra) : "r"(loc), "r"(r));
            asm volatile("st.shared::cluster.f32 [%0], %1;" :: "r"(ra), "f"(hn) : "memory");
        }

        // ---- prefetch x_{t+1} into next buffer's x-section (local only) ----
        if (t + 1 < SEQ) {
            int bbx = tid >> 5;            // 0..7
            int k   = (tid & 31) * 2;      // 0..62
            const float2 xv = *(const float2*)(x + ((size_t)(t + 1) * BATCH + b0 + bbx) * IND + k);
            *(float2*)(nxt + bbx * WSTR + HID + k) = xv;
        }

        // one cluster barrier per step: release h_t writes, acquire peers' h_t
        asm volatile("barrier.cluster.arrive.aligned;" ::: "memory");
        asm volatile("barrier.cluster.wait.aligned;" ::: "memory");

        // ---- fused readout: out[t, b0+ob, s*8+oo] = b_out + W_out . h_t ----
        if (tid < 64) {
            const ulonglong2* hh = (const ulonglong2*)(nxt + ob * WSTR);
            const ulonglong2* wo = (const ulonglong2*)(wout + oo * OSTR);
            unsigned long long ac = pk2(bout, 0.f);
            #pragma unroll 8
            for (int k = 0; k < HID / 4; ++k) {
                ulonglong2 h = hh[k];
                ulonglong2 w = wo[k];
                ac = ffma2(w.x, h.x, ac);
                ac = ffma2(w.y, h.y, ac);
            }
            out[((size_t)t * BATCH + b0 + ob) * OUTD + (int)s * 8 + oo] = hsum2(ac);
        }
    }
}

extern "C" void kernel_launch(void* const* d_in, const int* in_sizes, int n_in,
                              void* d_out, int out_size) {
    const float* x     = (const float*)d_in[0];
    const float* h0    = (const float*)d_in[1];
    const float* c0    = (const float*)d_in[2];
    const float* W_ih  = (const float*)d_in[3];
    const float* W_hh  = (const float*)d_in[4];
    const float* b     = (const float*)d_in[5];
    const float* W_out = (const float*)d_in[6];
    const float* b_out = (const float*)d_in[7];
    float* out = (float*)d_out;

    cudaFuncSetAttribute(lstm_persistent_kernel,
                         cudaFuncAttributeMaxDynamicSharedMemorySize, SM_BYTES);

    const int grid = (BATCH / BG) * S_CTAS;  // 16 groups x 8 slices = 128 CTAs
    lstm_persistent_kernel<<<grid, NTHREADS, SM_BYTES>>>(
        x, h0, c0, W_ih, W_hh, b, W_out, b_out, out);
}

// round 5
// speedup vs baseline: 1.0010x; 1.0010x over previous
#include <cuda_runtime.h>
#include <cstdint>

#define SEQ 2048
#define BATCH 128
#define IND 64
#define HID 256
#define OUTD 64
#define S_CTAS 8        // cluster size = hidden-slice CTAs per batch group
#define BG 8            // batch elements per group
#define UPC 32          // hidden units per CTA (HID / S_CTAS)
#define KTOT 320        // HID + IND (concatenated [h | x] dot length)
#define WSTR 324        // padded row stride in floats (mod 32 == 4 -> conflict-free)
#define OSTR 260        // padded W_out row stride
#define NTHREADS 256

// shared memory layout (in floats)
#define SM_WS   0                         // 128 rows x WSTR  (W_hh|W_ih slice)
#define SM_HX   (128 * WSTR)              // 2 buffers x BG x WSTR ([h|x] per batch)
#define SM_WOUT (SM_HX + 2 * BG * WSTR)   // 8 rows x OSTR (W_out slice)
#define SM_FLOATS (SM_WOUT + 8 * OSTR)
#define SM_BYTES (SM_FLOATS * 4)          // 194944 bytes

__device__ __forceinline__ uint32_t s2u(const void* p) {
    uint32_t a;
    asm("{ .reg .u64 t; cvta.to.shared.u64 t, %1; cvt.u32.u64 %0, t; }"
        : "=r"(a) : "l"(p));
    return a;
}
__device__ __forceinline__ unsigned long long ffma2(unsigned long long a,
                                                    unsigned long long b,
                                                    unsigned long long c) {
    unsigned long long d;
    asm("fma.rn.f32x2 %0, %1, %2, %3;" : "=l"(d) : "l"(a), "l"(b), "l"(c));
    return d;
}
__device__ __forceinline__ unsigned long long pk2(float x, float y) {
    unsigned long long r;
    asm("mov.b64 %0, {%1,%2};" : "=l"(r) : "f"(x), "f"(y));
    return r;
}
__device__ __forceinline__ float hsum2(unsigned long long v) {
    float x, y;
    asm("mov.b64 {%0,%1}, %2;" : "=f"(x), "=f"(y) : "l"(v));
    return x + y;
}

extern "C" __global__ void __cluster_dims__(S_CTAS, 1, 1) __launch_bounds__(NTHREADS, 1)
lstm_persistent_kernel(const float* __restrict__ x,
                       const float* __restrict__ h0,
                       const float* __restrict__ c0,
                       const float* __restrict__ W_ih,
                       const float* __restrict__ W_hh,
                       const float* __restrict__ bias,
                       const float* __restrict__ W_out,
                       const float* __restrict__ b_out,
                       float* __restrict__ out) {
    extern __shared__ float sm[];
    float* ws   = sm + SM_WS;
    float* hx0  = sm + SM_HX;
    float* hx1  = hx0 + BG * WSTR;
    float* wout = sm + SM_WOUT;

    const int tid = threadIdx.x;
    const int g   = blockIdx.x / S_CTAS;   // batch group
    uint32_t s;
    asm("mov.u32 %0, %%cluster_ctarank;" : "=r"(s));
    const int b0 = g * BG;
    const int u  = tid >> 3;               // hidden unit within slice (0..31)
    const int bb = tid & 7;                // batch within group (0..7)

    // ---------------- one-time init: weights / state into SMEM ----------------
    // combined gate rows: row r = gate*32 + uu -> global gate row gate*HID + s*32 + uu
    for (int i = tid; i < 128 * KTOT; i += NTHREADS) {
        int r = i / KTOT, k = i - r * KTOT;
        int gate = r >> 5, uu = r & 31;
        int grow = gate * HID + (int)s * UPC + uu;
        float v = (k < HID) ? W_hh[grow * HID + k] : W_ih[grow * IND + (k - HID)];
        ws[r * WSTR + k] = v;
    }
    for (int i = tid; i < 8 * HID; i += NTHREADS) {
        int oo = i >> 8, k = i & 255;
        wout[oo * OSTR + k] = W_out[((int)s * 8 + oo) * HID + k];
    }
    // h0 into buffer 0 (full h for this batch group)
    for (int i = tid; i < BG * HID; i += NTHREADS) {
        int bbx = i >> 8, k = i & 255;
        hx0[bbx * WSTR + k] = h0[(b0 + bbx) * HID + k];
    }
    // x_0 into buffer 0 x-section
    for (int i = tid; i < BG * IND; i += NTHREADS) {
        int bbx = i >> 6, k = i & 63;
        hx0[bbx * WSTR + HID + k] = x[(size_t)(b0 + bbx) * IND + k];
    }
    // per-thread constants
    float c_st = c0[(b0 + bb) * HID + (int)s * UPC + u];
    const float bi = bias[0 * HID + (int)s * UPC + u];
    const float bf = bias[1 * HID + (int)s * UPC + u];
    const float bg = bias[2 * HID + (int)s * UPC + u];
    const float bo = bias[3 * HID + (int)s * UPC + u];
    const int oo = tid & 7;        // readout: output column within slice
    const int ob = tid >> 3;       // readout: batch index (valid for tid<64)
    const float bout = (tid < 64) ? b_out[(int)s * 8 + oo] : 0.f;

    __syncthreads();
    asm volatile("barrier.cluster.arrive.aligned;" ::: "memory");
    asm volatile("barrier.cluster.wait.aligned;" ::: "memory");

    const uint32_t smem_b = s2u(sm);
    const int jmine = (int)s * UPC + u;    // my global hidden index

    const ulonglong2* wp0 = (const ulonglong2*)(ws + (0 * UPC + u) * WSTR);
    const ulonglong2* wp1 = (const ulonglong2*)(ws + (1 * UPC + u) * WSTR);
    const ulonglong2* wp2 = (const ulonglong2*)(ws + (2 * UPC + u) * WSTR);
    const ulonglong2* wp3 = (const ulonglong2*)(ws + (3 * UPC + u) * WSTR);

    for (int t = 0; t < SEQ; ++t) {
        float* cur = (t & 1) ? hx1 : hx0;
        float* nxt = (t & 1) ? hx0 : hx1;

        // ---- gate dots over K = 320 ([h_{t-1} | x_t]), packed f32x2 FMA ----
        const ulonglong2* hp = (const ulonglong2*)(cur + bb * WSTR);
        unsigned long long a0 = pk2(bi, 0.f);
        unsigned long long a1 = pk2(bf, 0.f);
        unsigned long long a2 = pk2(bg, 0.f);
        unsigned long long a3 = pk2(bo, 0.f);
        #pragma unroll 8
        for (int k = 0; k < KTOT / 4; ++k) {
            ulonglong2 h = hp[k];
            ulonglong2 w;
            w = wp0[k]; a0 = ffma2(w.x, h.x, a0); a0 = ffma2(w.y, h.y, a0);
            w = wp1[k]; a1 = ffma2(w.x, h.x, a1); a1 = ffma2(w.y, h.y, a1);
            w = wp2[k]; a2 = ffma2(w.x, h.x, a2); a2 = ffma2(w.y, h.y, a2);
            w = wp3[k]; a3 = ffma2(w.x, h.x, a3); a3 = ffma2(w.y, h.y, a3);
        }
        float li = hsum2(a0), lf = hsum2(a1), lg = hsum2(a2), lo = hsum2(a3);

        // ---- LSTM cell epilogue (eqx gate order i,f,g,o) ----
        float ig = 1.f / (1.f + __expf(-li));
        float fg = 1.f / (1.f + __expf(-lf));
        float gg = tanhf(lg);
        float og = 1.f / (1.f + __expf(-lo));
        c_st = fg * c_st + ig * gg;
        float hn = og * tanhf(c_st);

        // ---- scatter h_t to every cluster CTA's next buffer (DSMEM) ----
        uint32_t loc = smem_b + (uint32_t)((nxt - sm) + bb * WSTR + jmine) * 4u;
        #pragma unroll
        for (int r = 0; r < S_CTAS; ++r) {
            uint32_t ra;
            asm("mapa.shared::cluster.u32 %0, %1, %2;" : "=r"(ra) : "r"(loc), "r"(r));
            asm volatile("st.shared::cluster.f32 [%0], %1;" :: "r"(ra), "f"(hn) : "memory");
        }

        // ---- prefetch x_{t+1} into next buffer's x-section (local only) ----
        if (t + 1 < SEQ) {
            int bbx = tid >> 5;            // 0..7
            int k   = (tid & 31) * 2;      // 0..62
            const float2 xv = *(const float2*)(x + ((size_t)(t + 1) * BATCH + b0 + bbx) * IND + k);
            *(float2*)(nxt + bbx * WSTR + HID + k) = xv;
        }

        // one cluster barrier per step: release h_t writes, acquire peers' h_t
        asm volatile("barrier.cluster.arrive.aligned;" ::: "memory");
        asm volatile("barrier.cluster.wait.aligned;" ::: "memory");

        // ---- fused readout: out[t, b0+ob, s*8+oo] = b_out + W_out . h_t ----
        if (tid < 64) {
            const ulonglong2* hh = (const ulonglong2*)(nxt + ob * WSTR);
            const ulonglong2* wo = (const ulonglong2*)(wout + oo * OSTR);
            unsigned long long ac = pk2(bout, 0.f);
            #pragma unroll 8
            for (int k = 0; k < HID / 4; ++k) {
                ulonglong2 h = hh[k];
                ulonglong2 w = wo[k];
                ac = ffma2(w.x, h.x, ac);
                ac = ffma2(w.y, h.y, ac);
            }
            out[((size_t)t * BATCH + b0 + ob) * OUTD + (int)s * 8 + oo] = hsum2(ac);
        }
    }
}

extern "C" void kernel_launch(void* const* d_in, const int* in_sizes, int n_in,
                              void* d_out, int out_size) {
    const float* x     = (const float*)d_in[0];
    const float* h0    = (const float*)d_in[1];
    const float* c0    = (const float*)d_in[2];
    const float* W_ih  = (const float*)d_in[3];
    const float* W_hh  = (const float*)d_in[4];
    const float* b     = (const float*)d_in[5];
    const float* W_out = (const float*)d_in[6];
    const float* b_out = (const float*)d_in[7];
    float* out = (float*)d_out;

    cudaFuncSetAttribute(lstm_persistent_kernel,
                         cudaFuncAttributeMaxDynamicSharedMemorySize, SM_BYTES);

    const int grid = (BATCH / BG) * S_CTAS;  // 16 groups x 8 slices = 128 CTAs
    lstm_persistent_kernel<<<grid, NTHREADS, SM_BYTES>>>(
        x, h0, c0, W_ih, W_hh, b, W_out, b_out, out);
}

// round 10
// speedup vs baseline: 1.0069x; 1.0059x over previous
#include <cuda_runtime.h>
#include <cstdint>

#define SEQ 2048
#define BATCH 128
#define IND 64
#define HID 256
#define OUTD 64
#define S_CTAS 8        // cluster size = hidden-slice CTAs per batch group
#define BG 8            // batch elements per group
#define UPC 32          // hidden units per CTA (HID / S_CTAS)
#define KTOT 320        // HID + IND (concatenated [h | x] dot length)
#define KHALF 160       // split-K half length
#define WSTR 324        // padded row stride in floats (mod 32 == 4 -> conflict-free)
#define OSTR 260        // padded W_out row stride
#define NTHREADS 512

// shared memory layout (in floats)
#define SM_WS    0                          // 128 rows x WSTR  (W_hh|W_ih slice)
#define SM_HX    (128 * WSTR)               // 2 buffers x BG x WSTR ([h|x] per batch)
#define SM_WOUT  (SM_HX + 2 * BG * WSTR)    // 8 rows x OSTR (W_out slice)
#define SM_STAGE (SM_WOUT + 8 * OSTR)       // 256 x 12 floats (split-K partials, padded)
#define SM_FLOATS (SM_STAGE + 256 * 12)
#define SM_BYTES (SM_FLOATS * 4)            // 207232 bytes

__device__ __forceinline__ uint32_t s2u(const void* p) {
    uint32_t a;
    asm("{ .reg .u64 t; cvta.to.shared.u64 t, %1; cvt.u32.u64 %0, t; }"
        : "=r"(a) : "l"(p));
    return a;
}
__device__ __forceinline__ unsigned long long ffma2(unsigned long long a,
                                                    unsigned long long b,
                                                    unsigned long long c) {
    unsigned long long d;
    asm("fma.rn.f32x2 %0, %1, %2, %3;" : "=l"(d) : "l"(a), "l"(b), "l"(c));
    return d;
}
__device__ __forceinline__ unsigned long long addf2(unsigned long long a,
                                                    unsigned long long b) {
    unsigned long long d;
    asm("add.rn.f32x2 %0, %1, %2;" : "=l"(d) : "l"(a), "l"(b));
    return d;
}
__device__ __forceinline__ unsigned long long pk2(float x, float y) {
    unsigned long long r;
    asm("mov.b64 %0, {%1,%2};" : "=l"(r) : "f"(x), "f"(y));
    return r;
}
__device__ __forceinline__ float hsum2(unsigned long long v) {
    float x, y;
    asm("mov.b64 {%0,%1}, %2;" : "=f"(x), "=f"(y) : "l"(v));
    return x + y;
}
__device__ __forceinline__ float tanh_ap(float x) {
    float y;
    asm("tanh.approx.f32 %0, %1;" : "=f"(y) : "f"(x));
    return y;
}
__device__ __forceinline__ float sigm_ap(float x) {
    return 0.5f * tanh_ap(0.5f * x) + 0.5f;
}

extern "C" __global__ void __cluster_dims__(S_CTAS, 1, 1) __launch_bounds__(NTHREADS, 1)
lstm_persistent_kernel(const float* __restrict__ x,
                       const float* __restrict__ h0,
                       const float* __restrict__ c0,
                       const float* __restrict__ W_ih,
                       const float* __restrict__ W_hh,
                       const float* __restrict__ bias,
                       const float* __restrict__ W_out,
                       const float* __restrict__ b_out,
                       float* __restrict__ out) {
    extern __shared__ float sm[];
    float* ws    = sm + SM_WS;
    float* hx0   = sm + SM_HX;
    float* hx1   = hx0 + BG * WSTR;
    float* wout  = sm + SM_WOUT;
    float* stage = sm + SM_STAGE;

    const int tid = threadIdx.x;
    const int g   = blockIdx.x / S_CTAS;   // batch group
    uint32_t s;
    asm("mov.u32 %0, %%cluster_ctarank;" : "=r"(s));
    const int b0 = g * BG;
    const int kh = tid >> 8;               // split-K half (0 or 1)
    const int p  = tid & 255;              // (u, bb) index
    const int u  = p >> 3;                 // hidden unit within slice (0..31)
    const int bb = p & 7;                  // batch within group (0..7)

    // ---------------- one-time init: weights / state into SMEM ----------------
    for (int i = tid; i < 128 * KTOT; i += NTHREADS) {
        int r = i / KTOT, k = i - r * KTOT;
        int gate = r >> 5, uu = r & 31;
        int grow = gate * HID + (int)s * UPC + uu;
        float v = (k < HID) ? W_hh[grow * HID + k] : W_ih[grow * IND + (k - HID)];
        ws[r * WSTR + k] = v;
    }
    for (int i = tid; i < 8 * HID; i += NTHREADS) {
        int oo = i >> 8, k = i & 255;
        wout[oo * OSTR + k] = W_out[((int)s * 8 + oo) * HID + k];
    }
    for (int i = tid; i < BG * HID; i += NTHREADS) {
        int bbx = i >> 8, k = i & 255;
        hx0[bbx * WSTR + k] = h0[(b0 + bbx) * HID + k];
    }
    for (int i = tid; i < BG * IND; i += NTHREADS) {
        int bbx = i >> 6, k = i & 63;
        hx0[bbx * WSTR + HID + k] = x[(size_t)(b0 + bbx) * IND + k];
    }
    // per-thread constants (cell state / bias only used by kh==0 threads)
    float c_st = c0[(b0 + bb) * HID + (int)s * UPC + u];
    const float bi = bias[0 * HID + (int)s * UPC + u];
    const float bf = bias[1 * HID + (int)s * UPC + u];
    const float bg = bias[2 * HID + (int)s * UPC + u];
    const float bo = bias[3 * HID + (int)s * UPC + u];
    // readout mapping: warps 14-15 (tid 448..511)
    const int ridx = tid - 448;                 // 0..63 when valid
    const int ob = (ridx >= 0) ? (ridx >> 3) : 0;
    const int oo = ridx & 7;
    const float bout = (ridx >= 0) ? b_out[(int)s * 8 + oo] : 0.f;

    __syncthreads();
    asm volatile("barrier.cluster.arrive.aligned;" ::: "memory");
    asm volatile("barrier.cluster.wait.aligned;" ::: "memory");

    const uint32_t smem_b = s2u(sm);
    const int jmine = (int)s * UPC + u;    // my global hidden index

    const int koff = kh * KHALF;           // this thread's K-range start (floats)
    const ulonglong2* wp0 = (const ulonglong2*)(ws + (0 * UPC + u) * WSTR + koff);
    const ulonglong2* wp1 = (const ulonglong2*)(ws + (1 * UPC + u) * WSTR + koff);
    const ulonglong2* wp2 = (const ulonglong2*)(ws + (2 * UPC + u) * WSTR + koff);
    const ulonglong2* wp3 = (const ulonglong2*)(ws + (3 * UPC + u) * WSTR + koff);

    // x-prefetch mapping (kh==0 threads only: 256 threads x float2 = 8 x 64 floats)
    const int pxb = p >> 5;               // 0..7
    const int pxk = (p & 31) * 2;         // 0..62

    for (int t = 0; t < SEQ; ++t) {
        float* cur = (t & 1) ? hx1 : hx0;
        float* nxt = (t & 1) ? hx0 : hx1;

        // ---- early x_{t+1} prefetch into registers (overlaps gate loop) ----
        float2 xv = make_float2(0.f, 0.f);
        const bool do_x = (kh == 0) && (t + 1 < SEQ);
        if (do_x)
            xv = *(const float2*)(x + ((size_t)(t + 1) * BATCH + b0 + pxb) * IND + pxk);

        // ---- partial gate dots over K-half (packed f32x2 FMA) ----
        const ulonglong2* hp = (const ulonglong2*)(cur + bb * WSTR + koff);
        unsigned long long a0 = (kh == 0) ? pk2(bi, 0.f) : 0ull;
        unsigned long long a1 = (kh == 0) ? pk2(bf, 0.f) : 0ull;
        unsigned long long a2 = (kh == 0) ? pk2(bg, 0.f) : 0ull;
        unsigned long long a3 = (kh == 0) ? pk2(bo, 0.f) : 0ull;
        #pragma unroll 8
        for (int k = 0; k < KHALF / 4; ++k) {
            ulonglong2 h = hp[k];
            ulonglong2 w;
            w = wp0[k]; a0 = ffma2(w.x, h.x, a0); a0 = ffma2(w.y, h.y, a0);
            w = wp1[k]; a1 = ffma2(w.x, h.x, a1); a1 = ffma2(w.y, h.y, a1);
            w = wp2[k]; a2 = ffma2(w.x, h.x, a2); a2 = ffma2(w.y, h.y, a2);
            w = wp3[k]; a3 = ffma2(w.x, h.x, a3); a3 = ffma2(w.y, h.y, a3);
        }

        if (kh == 1) {
            // publish partials (padded stride 12 floats -> .128 conflict floor)
            ulonglong2* st = (ulonglong2*)(stage + p * 12);
            st[0] = make_ulonglong2(a0, a1);
            st[1] = make_ulonglong2(a2, a3);
        } else if (do_x) {
            // store prefetched x_{t+1} (local x-section of next buffer)
            *(float2*)(nxt + pxb * WSTR + HID + pxk) = xv;
        }
        __syncthreads();

        if (kh == 0) {
            const ulonglong2* st = (const ulonglong2*)(stage + p * 12);
            ulonglong2 q0 = st[0], q1 = st[1];
            float li = hsum2(addf2(a0, q0.x));
            float lf = hsum2(addf2(a1, q0.y));
            float lg = hsum2(addf2(a2, q1.x));
            float lo = hsum2(addf2(a3, q1.y));

            // ---- LSTM cell epilogue (eqx gate order i,f,g,o) ----
            float ig = sigm_ap(li);
            float fg = sigm_ap(lf);
            float gg = tanh_ap(lg);
            float og = sigm_ap(lo);
            c_st = fg * c_st + ig * gg;
            float hn = og * tanh_ap(c_st);

            // ---- scatter h_t to every cluster CTA's next buffer (DSMEM) ----
            uint32_t loc = smem_b + (uint32_t)((nxt - sm) + bb * WSTR + jmine) * 4u;
            #pragma unroll
            for (int r = 0; r < S_CTAS; ++r) {
                uint32_t ra;
                asm("mapa.shared::cluster.u32 %0, %1, %2;" : "=r"(ra) : "r"(loc), "r"(r));
                asm volatile("st.shared::cluster.f32 [%0], %1;" :: "r"(ra), "f"(hn) : "memory");
            }
        }

        // one cluster barrier per step: release h_t writes, acquire peers' h_t
        asm volatile("barrier.cluster.arrive.aligned;" ::: "memory");
        asm volatile("barrier.cluster.wait.aligned;" ::: "memory");

        // ---- fused readout on warps 14-15: out[t, b0+ob, s*8+oo] ----
        if (ridx >= 0) {
            const ulonglong2* hh = (const ulonglong2*)(nxt + ob * WSTR);
            const ulonglong2* wo = (const ulonglong2*)(wout + oo * OSTR);
            unsigned long long ac = pk2(bout, 0.f);
            #pragma unroll 8
            for (int k = 0; k < HID / 4; ++k) {
                ulonglong2 h = hh[k];
                ulonglong2 w = wo[k];
                ac = ffma2(w.x, h.x, ac);
                ac = ffma2(w.y, h.y, ac);
            }
            out[((size_t)t * BATCH + b0 + ob) * OUTD + (int)s * 8 + oo] = hsum2(ac);
        }
    }
}

extern "C" void kernel_launch(void* const* d_in, const int* in_sizes, int n_in,
                              void* d_out, int out_size) {
    const float* x     = (const float*)d_in[0];
    const float* h0    = (const float*)d_in[1];
    const float* c0    = (const float*)d_in[2];
    const float* W_ih  = (const float*)d_in[3];
    const float* W_hh  = (const float*)d_in[4];
    const float* b     = (const float*)d_in[5];
    const float* W_out = (const float*)d_in[6];
    const float* b_out = (const float*)d_in[7];
    float* out = (float*)d_out;

    cudaFuncSetAttribute(lstm_persistent_kernel,
                         cudaFuncAttributeMaxDynamicSharedMemorySize, SM_BYTES);

    const int grid = (BATCH / BG) * S_CTAS;  // 16 groups x 8 slices = 128 CTAs
    lstm_persistent_kernel<<<grid, NTHREADS, SM_BYTES>>>(
        x, h0, c0, W_ih, W_hh, b, W_out, b_out, out);
}